// round 8
// baseline (speedup 1.0000x reference)
#include <cuda_runtime.h>

#define BB 4
#define SS 512
#define HH 128

// 512 blocks x 512 threads, 3 blocks/SM. Block owns 4 output rows (t0..t0+3).
// Thread (h = tid&127, q = tid>>7) accumulates the 14 live dot products
// over k-quarter q. Row data transposed in smem: rows2[k][r] = {x, ref},
// r = 0..4 (padded to 8) so each k-iter is 3 LDS.128 broadcasts.
__global__ __launch_bounds__(512, 3) void align_kernel(
    const float* __restrict__ x, const float* __restrict__ ref,
    const float* __restrict__ Wa, const float* __restrict__ Wb,
    const float* __restrict__ b1, const float* __restrict__ W2,
    const float* __restrict__ b2, const float* __restrict__ Wp1,
    const float* __restrict__ bp1, const float* __restrict__ Wp2,
    const float* __restrict__ bp2, float* __restrict__ out)
{
    const int tid = threadIdx.x;
    const int q   = tid >> 7;        // k-quarter 0..3
    const int h   = tid & 127;       // hidden column
    const int g0  = blockIdx.x * 4;
    const int b   = g0 >> 9;
    const int t0  = g0 & (SS - 1);

    __shared__ float2 rows2[HH][8];      // [k][r] {x, ref}, r=0..4 valid, padded to 8
    __shared__ float  part[3][14][HH];   // partials from q = 1..3
    __shared__ float  red[4][24];
    __shared__ float  rowvals[4][2];

    // ---- stage rows transposed: 5 rows x 128 k ----
    for (int idx = tid; idx < 5 * HH; idx += 512) {
        const int r = idx >> 7;          // row 0..4
        const int k = idx & 127;
        int t  = t0 - 1 + r;
        int tc = t < 0 ? 0 : t;
        const size_t gi = (size_t)(b * SS + tc) * HH + k;
        rows2[k][r] = make_float2(x[gi], ref[gi]);
    }
    // zero the padding lanes once (so LDS.128 over r=4..5 reads defined data)
    for (int idx = tid; idx < HH; idx += 512) {
        rows2[idx][5] = make_float2(0.f, 0.f);
    }
    __syncthreads();

    // ---- k-quarter mainloop ----
    float A[5], C[5], P[4];
    const float ab = (q == 0) ? b1[h]  : 0.0f;
    const float pb = (q == 0) ? bp1[h] : 0.0f;
    #pragma unroll
    for (int r = 0; r < 5; r++) { A[r] = ab; C[r] = 0.0f; }
    #pragma unroll
    for (int r = 0; r < 4; r++) P[r] = pb;

    const int kbase = q * 32;
    #pragma unroll 4
    for (int kk = 0; kk < 32; kk++) {
        const int k = kbase + kk;
        const float wa = Wa[k * HH + h];
        const float wb = Wb[k * HH + h];
        const float wp = Wp1[k * HH + h];
        // three 16B broadcasts: rows (0,1), (2,3), (4,pad)
        const float4 v01 = *(const float4*)&rows2[k][0];
        const float4 v23 = *(const float4*)&rows2[k][2];
        const float4 v4p = *(const float4*)&rows2[k][4];
        const float x0 = v01.x, r0 = v01.y, x1 = v01.z, r1 = v01.w;
        const float x2 = v23.x, r2 = v23.y, x3 = v23.z, r3 = v23.w;
        const float x4 = v4p.x, r4 = v4p.y;
        A[0] = fmaf(x0, wa, A[0]);
        A[1] = fmaf(x1, wa, A[1]);
        A[2] = fmaf(x2, wa, A[2]);
        A[3] = fmaf(x3, wa, A[3]);
        A[4] = fmaf(x4, wa, A[4]);
        C[0] = fmaf(r0, wb, C[0]);
        C[1] = fmaf(r1, wb, C[1]);
        C[2] = fmaf(r2, wb, C[2]);
        C[3] = fmaf(r3, wb, C[3]);
        C[4] = fmaf(r4, wb, C[4]);
        P[0] = fmaf(x1, wp, P[0]);
        P[1] = fmaf(x2, wp, P[1]);
        P[2] = fmaf(x3, wp, P[2]);
        P[3] = fmaf(x4, wp, P[3]);
    }

    // ---- publish partials (q = 1..3) ----
    if (q != 0) {
        #pragma unroll
        for (int r = 0; r < 5; r++) {
            part[q - 1][r][h]     = A[r];
            part[q - 1][5 + r][h] = C[r];
        }
        #pragma unroll
        for (int r = 0; r < 4; r++) part[q - 1][10 + r][h] = P[r];
    }
    __syncthreads();

    if (q == 0) {
        // ---- combine ----
        #pragma unroll
        for (int r = 0; r < 5; r++) {
            A[r] += part[0][r][h] + part[1][r][h] + part[2][r][h];
            C[r] += part[0][5 + r][h] + part[1][5 + r][h] + part[2][5 + r][h];
        }
        #pragma unroll
        for (int r = 0; r < 4; r++) {
            P[r] += part[0][10 + r][h] + part[1][10 + r][h] + part[2][10 + r][h];
            P[r]  = fmaxf(P[r], 0.0f);
        }

        const float w2   = W2[h];
        const float wp20 = Wp2[h * 3 + 0];
        const float wp21 = Wp2[h * 3 + 1];
        const float wp22 = Wp2[h * 3 + 2];

        const int wid  = tid >> 5;   // 0..3 within q==0 slice
        const int lane = tid & 31;

        #pragma unroll
        for (int i = 0; i < 4; i++) {
            float v[6];
            v[0] = fmaxf(A[i + 1] + C[i + 1], 0.0f) * w2;  // A[t, t]
            v[1] = fmaxf(A[i]     + C[i + 1], 0.0f) * w2;  // A[t-1, t]  (insert)
            v[2] = fmaxf(A[i + 1] + C[i],     0.0f) * w2;  // A[t, t-1]  (delete)
            v[3] = P[i] * wp20;
            v[4] = P[i] * wp21;
            v[5] = P[i] * wp22;
            #pragma unroll
            for (int j = 0; j < 6; j++) {
                float s = v[j];
                s += __shfl_xor_sync(0xffffffffu, s, 16);
                s += __shfl_xor_sync(0xffffffffu, s, 8);
                s += __shfl_xor_sync(0xffffffffu, s, 4);
                s += __shfl_xor_sync(0xffffffffu, s, 2);
                s += __shfl_xor_sync(0xffffffffu, s, 1);
                if (lane == 0) red[wid][i * 6 + j] = s;
            }
        }
        asm volatile("bar.sync 1, 128;" ::: "memory");

        if (tid < 32) {
            float s = 0.0f;
            if (lane < 24)
                s = red[0][lane] + red[1][lane] + red[2][lane] + red[3][lane];
            const float s0 = __shfl_sync(0xffffffffu, s, lane * 6 + 0);
            const float s1 = __shfl_sync(0xffffffffu, s, lane * 6 + 1);
            const float s2 = __shfl_sync(0xffffffffu, s, lane * 6 + 2);
            const float s3 = __shfl_sync(0xffffffffu, s, lane * 6 + 3);
            const float s4 = __shfl_sync(0xffffffffu, s, lane * 6 + 4);
            const float s5 = __shfl_sync(0xffffffffu, s, lane * 6 + 5);
            if (lane < 4) {
                const int t = t0 + lane;
                float op_code, alpha;
                const float Ad = 1.0f / (1.0f + expf(-(s0 + b2[0])));
                if (t == 0) {
                    op_code = -1.0f; alpha = 0.0f;
                } else {
                    const float Ai   = 1.0f / (1.0f + expf(-(s1 + b2[0])));
                    const float Adel = 1.0f / (1.0f + expf(-(s2 + b2[0])));
                    const float l0 = s3 + bp2[0];
                    const float l1 = s4 + bp2[1];
                    const float l2 = s5 + bp2[2];
                    const float mx  = fmaxf(l0, fmaxf(l1, l2));
                    const float lse = mx + logf(expf(l0 - mx) + expf(l1 - mx) + expf(l2 - mx));
                    const float m   = Ad   * (l0 - lse);
                    const float ins = Ai   * (l1 - lse);
                    const float del = Adel * (l2 - lse);
                    int op;
                    if (m >= ins && m >= del) op = 0;  // first-max == jnp.argmax
                    else if (ins >= del)      op = 1;
                    else                      op = 2;
                    op_code = (float)op;
                    alpha   = Ad;
                }
                rowvals[lane][0] = op_code;
                rowvals[lane][1] = alpha;
            }
        }
    }
    __syncthreads();

    // ---- output: thread (i = tid>>7, h = tid&127) writes one element ----
    {
        const int i = tid >> 7;
        const float fop   = rowvals[i][0];
        const float alpha = rowvals[i][1];
        const float2 cur  = rows2[h][i + 1];
        const float  xm1  = rows2[h][i].x;
        float o;
        if (fop < -0.5f)      o = cur.x;                                  // t == 0
        else if (fop < 0.5f)  o = (1.0f - alpha) * cur.x + alpha * cur.y; // match
        else if (fop < 1.5f)  o = cur.y;                                  // insert
        else                  o = xm1;                                    // delete
        out[(size_t)(b * SS + t0 + i) * HH + h] = o;
    }
}

extern "C" void kernel_launch(void* const* d_in, const int* in_sizes, int n_in,
                              void* d_out, int out_size) {
    const float* x   = (const float*)d_in[0];
    const float* ref = (const float*)d_in[1];
    const float* Wa  = (const float*)d_in[2];
    const float* Wb  = (const float*)d_in[3];
    const float* b1  = (const float*)d_in[4];
    const float* W2  = (const float*)d_in[5];
    const float* b2  = (const float*)d_in[6];
    const float* Wp1 = (const float*)d_in[7];
    const float* bp1 = (const float*)d_in[8];
    const float* Wp2 = (const float*)d_in[9];
    const float* bp2 = (const float*)d_in[10];

    dim3 grid(BB * SS / 4);   // 512 blocks
    dim3 block(512);          // 128 h-threads x 4 k-quarters
    align_kernel<<<grid, block>>>(x, ref, Wa, Wb, b1, W2, b2,
                                  Wp1, bp1, Wp2, bp2, (float*)d_out);
}

// round 10
// speedup vs baseline: 1.0960x; 1.0960x over previous
#include <cuda_runtime.h>

#define BB 4
#define SS 512
#define HH 128

// 512 blocks x 256 threads. Block owns 4 output rows (t0..t0+3).
// Thread (hp = tid&63, q = tid>>6) owns h-pair {2hp, 2hp+1}, k-quarter q.
// 28 scalar fp32 accumulators (14 live dots x 2 h).
// Rows staged transposed: rows2[k][12] = {x0..x4,pad, r0..r4,pad} so each
// k-iter is 3 LDS.128 broadcasts + 3 LDG.64 weight loads + 28 FMAs.
__global__ __launch_bounds__(256, 3) void align_kernel(
    const float* __restrict__ x, const float* __restrict__ ref,
    const float* __restrict__ Wa, const float* __restrict__ Wb,
    const float* __restrict__ b1, const float* __restrict__ W2,
    const float* __restrict__ b2, const float* __restrict__ Wp1,
    const float* __restrict__ bp1, const float* __restrict__ Wp2,
    const float* __restrict__ bp2, float* __restrict__ out)
{
    const int tid = threadIdx.x;
    const int q   = tid >> 6;        // k-quarter 0..3
    const int hp  = tid & 63;        // h-pair index (h = 2hp, 2hp+1)
    const int g0  = blockIdx.x * 4;
    const int b   = g0 >> 9;
    const int t0  = g0 & (SS - 1);

    __shared__ float rows2[HH][12];     // [k][x0..x4,pad, r0..r4,pad]
    __shared__ float part[3][28][64];   // partials from q = 1..3
    __shared__ float red[2][24];
    __shared__ float rowvals[4][2];

    // ---- stage rows transposed ----
    for (int idx = tid; idx < 5 * HH; idx += 256) {
        const int r = idx >> 7;          // row 0..4  (global t0-1+r)
        const int k = idx & 127;
        int t  = t0 - 1 + r;
        int tc = t < 0 ? 0 : t;
        const size_t gi = (size_t)(b * SS + tc) * HH + k;
        rows2[k][r]     = x[gi];
        rows2[k][6 + r] = ref[gi];
    }
    __syncthreads();

    // ---- mainloop: this thread's 32 k, 28 accumulators ----
    float A[5][2], C[5][2], P[4][2];
    {
        const float2 ab = (q == 0) ? ((const float2*)b1)[hp]  : make_float2(0.f, 0.f);
        const float2 pb = (q == 0) ? ((const float2*)bp1)[hp] : make_float2(0.f, 0.f);
        #pragma unroll
        for (int r = 0; r < 5; r++) {
            A[r][0] = ab.x; A[r][1] = ab.y;
            C[r][0] = 0.f;  C[r][1] = 0.f;
        }
        #pragma unroll
        for (int r = 0; r < 4; r++) { P[r][0] = pb.x; P[r][1] = pb.y; }
    }

    const float2* __restrict__ Wa2 = (const float2*)Wa;   // [k*64 + hp]
    const float2* __restrict__ Wb2 = (const float2*)Wb;
    const float2* __restrict__ Wp  = (const float2*)Wp1;

    const int kbase = q * 32;
    #pragma unroll 4
    for (int kk = 0; kk < 32; kk++) {
        const int k = kbase + kk;
        const float2 wa = Wa2[k * 64 + hp];
        const float2 wb = Wb2[k * 64 + hp];
        const float2 wp = Wp [k * 64 + hp];
        const float4 u0 = *(const float4*)&rows2[k][0];   // x0 x1 x2 x3
        const float4 u1 = *(const float4*)&rows2[k][4];   // x4 pad r0 r1
        const float4 u2 = *(const float4*)&rows2[k][8];   // r2 r3 r4 pad
        const float xv[5] = {u0.x, u0.y, u0.z, u0.w, u1.x};
        const float rv[5] = {u1.z, u1.w, u2.x, u2.y, u2.z};
        #pragma unroll
        for (int r = 0; r < 5; r++) {
            A[r][0] = fmaf(xv[r], wa.x, A[r][0]);
            A[r][1] = fmaf(xv[r], wa.y, A[r][1]);
            C[r][0] = fmaf(rv[r], wb.x, C[r][0]);
            C[r][1] = fmaf(rv[r], wb.y, C[r][1]);
        }
        #pragma unroll
        for (int r = 0; r < 4; r++) {
            P[r][0] = fmaf(xv[r + 1], wp.x, P[r][0]);
            P[r][1] = fmaf(xv[r + 1], wp.y, P[r][1]);
        }
    }

    // ---- publish partials (q = 1..3): dot index d = 0..27 ----
    if (q != 0) {
        #pragma unroll
        for (int r = 0; r < 5; r++) {
            part[q - 1][2 * r + 0][hp]  = A[r][0];
            part[q - 1][2 * r + 1][hp]  = A[r][1];
            part[q - 1][10 + 2 * r][hp] = C[r][0];
            part[q - 1][11 + 2 * r][hp] = C[r][1];
        }
        #pragma unroll
        for (int r = 0; r < 4; r++) {
            part[q - 1][20 + 2 * r][hp] = P[r][0];
            part[q - 1][21 + 2 * r][hp] = P[r][1];
        }
    }
    __syncthreads();

    if (q == 0) {
        // ---- combine ----
        #pragma unroll
        for (int r = 0; r < 5; r++) {
            A[r][0] += part[0][2*r][hp]    + part[1][2*r][hp]    + part[2][2*r][hp];
            A[r][1] += part[0][2*r+1][hp]  + part[1][2*r+1][hp]  + part[2][2*r+1][hp];
            C[r][0] += part[0][10+2*r][hp] + part[1][10+2*r][hp] + part[2][10+2*r][hp];
            C[r][1] += part[0][11+2*r][hp] + part[1][11+2*r][hp] + part[2][11+2*r][hp];
        }
        #pragma unroll
        for (int r = 0; r < 4; r++) {
            P[r][0] += part[0][20+2*r][hp] + part[1][20+2*r][hp] + part[2][20+2*r][hp];
            P[r][1] += part[0][21+2*r][hp] + part[1][21+2*r][hp] + part[2][21+2*r][hp];
            P[r][0]  = fmaxf(P[r][0], 0.f);
            P[r][1]  = fmaxf(P[r][1], 0.f);
        }

        const float2 w2p = ((const float2*)W2)[hp];
        const float  w2a[2] = {w2p.x, w2p.y};
        const float* wq = &Wp2[6 * hp];   // [h0: 0..2, h1: 3..5]

        const int wid  = tid >> 5;   // 0 or 1 (q==0 slice is tid 0..63)
        const int lane = tid & 31;

        #pragma unroll
        for (int i = 0; i < 4; i++) {
            float v[6] = {0.f, 0.f, 0.f, 0.f, 0.f, 0.f};
            #pragma unroll
            for (int j = 0; j < 2; j++) {
                v[0] += fmaxf(A[i + 1][j] + C[i + 1][j], 0.f) * w2a[j];  // A[t,t]
                v[1] += fmaxf(A[i][j]     + C[i + 1][j], 0.f) * w2a[j];  // A[t-1,t]
                v[2] += fmaxf(A[i + 1][j] + C[i][j],     0.f) * w2a[j];  // A[t,t-1]
                const float pj = P[i][j];
                v[3] += pj * wq[3 * j + 0];
                v[4] += pj * wq[3 * j + 1];
                v[5] += pj * wq[3 * j + 2];
            }
            #pragma unroll
            for (int j = 0; j < 6; j++) {
                float s = v[j];
                s += __shfl_xor_sync(0xffffffffu, s, 16);
                s += __shfl_xor_sync(0xffffffffu, s, 8);
                s += __shfl_xor_sync(0xffffffffu, s, 4);
                s += __shfl_xor_sync(0xffffffffu, s, 2);
                s += __shfl_xor_sync(0xffffffffu, s, 1);
                if (lane == 0) red[wid][i * 6 + j] = s;
            }
        }
        asm volatile("bar.sync 1, 64;" ::: "memory");

        if (tid < 32) {
            float s = 0.0f;
            if (lane < 24) s = red[0][lane] + red[1][lane];
            const float s0 = __shfl_sync(0xffffffffu, s, lane * 6 + 0);
            const float s1 = __shfl_sync(0xffffffffu, s, lane * 6 + 1);
            const float s2 = __shfl_sync(0xffffffffu, s, lane * 6 + 2);
            const float s3 = __shfl_sync(0xffffffffu, s, lane * 6 + 3);
            const float s4 = __shfl_sync(0xffffffffu, s, lane * 6 + 4);
            const float s5 = __shfl_sync(0xffffffffu, s, lane * 6 + 5);
            if (lane < 4) {
                const int t = t0 + lane;
                float op_code, alpha;
                const float Ad = 1.0f / (1.0f + expf(-(s0 + b2[0])));
                if (t == 0) {
                    op_code = -1.0f; alpha = 0.0f;
                } else {
                    const float Ai   = 1.0f / (1.0f + expf(-(s1 + b2[0])));
                    const float Adel = 1.0f / (1.0f + expf(-(s2 + b2[0])));
                    const float l0 = s3 + bp2[0];
                    const float l1 = s4 + bp2[1];
                    const float l2 = s5 + bp2[2];
                    const float mx  = fmaxf(l0, fmaxf(l1, l2));
                    const float lse = mx + logf(expf(l0 - mx) + expf(l1 - mx) + expf(l2 - mx));
                    const float m   = Ad   * (l0 - lse);
                    const float ins = Ai   * (l1 - lse);
                    const float del = Adel * (l2 - lse);
                    int op;
                    if (m >= ins && m >= del) op = 0;  // first-max == jnp.argmax
                    else if (ins >= del)      op = 1;
                    else                      op = 2;
                    op_code = (float)op;
                    alpha   = Ad;
                }
                rowvals[lane][0] = op_code;
                rowvals[lane][1] = alpha;
            }
        }
    }
    __syncthreads();

    // ---- output: 512 elements, 256 threads -> 2 each ----
    #pragma unroll
    for (int rep = 0; rep < 2; rep++) {
        const int idx = tid + rep * 256;
        const int i   = idx >> 7;        // row 0..3
        const int h   = idx & 127;
        const float fop   = rowvals[i][0];
        const float alpha = rowvals[i][1];
        const float cx  = rows2[h][i + 1];      // x[t0+i]
        const float cr  = rows2[h][6 + i + 1];  // ref[t0+i]
        const float px  = rows2[h][i];          // x[t0+i-1]
        float o;
        if (fop < -0.5f)      o = cx;                                  // t == 0
        else if (fop < 0.5f)  o = (1.0f - alpha) * cx + alpha * cr;    // match
        else if (fop < 1.5f)  o = cr;                                  // insert
        else                  o = px;                                  // delete
        out[(size_t)(b * SS + t0 + i) * HH + h] = o;
    }
}

extern "C" void kernel_launch(void* const* d_in, const int* in_sizes, int n_in,
                              void* d_out, int out_size) {
    const float* x   = (const float*)d_in[0];
    const float* ref = (const float*)d_in[1];
    const float* Wa  = (const float*)d_in[2];
    const float* Wb  = (const float*)d_in[3];
    const float* b1  = (const float*)d_in[4];
    const float* W2  = (const float*)d_in[5];
    const float* b2  = (const float*)d_in[6];
    const float* Wp1 = (const float*)d_in[7];
    const float* bp1 = (const float*)d_in[8];
    const float* Wp2 = (const float*)d_in[9];
    const float* bp2 = (const float*)d_in[10];

    dim3 grid(BB * SS / 4);   // 512 blocks
    dim3 block(256);          // 64 h-pairs x 4 k-quarters
    align_kernel<<<grid, block>>>(x, ref, Wa, Wb, b1, W2, b2,
                                  Wp1, bp1, Wp2, bp2, (float*)d_out);
}

// round 11
// speedup vs baseline: 1.3643x; 1.2448x over previous
#include <cuda_runtime.h>

#define BB 4
#define SS 512
#define HH 128

// 512 blocks x 128 threads. Block owns 4 output rows (t0..t0+3).
// Thread (hq = tid&31, q = tid>>5) owns h-quad {4hq..4hq+3}, k-quarter q (32 k).
// 56 scalar accumulators. Mainloop iter: 3 LDG.128 + 3 LDS.128 + 56 FMA.
// q==0 is ONE warp: combines partials, reduces, decides, writes float4 outputs.
__global__ __launch_bounds__(128) void align_kernel(
    const float* __restrict__ x, const float* __restrict__ ref,
    const float* __restrict__ Wa, const float* __restrict__ Wb,
    const float* __restrict__ b1, const float* __restrict__ W2,
    const float* __restrict__ b2, const float* __restrict__ Wp1,
    const float* __restrict__ bp1, const float* __restrict__ Wp2,
    const float* __restrict__ bp2, float* __restrict__ out)
{
    const int tid = threadIdx.x;
    const int q   = tid >> 5;        // k-quarter 0..3
    const int hq  = tid & 31;        // h-quad (h = 4hq .. 4hq+3)
    const int g0  = blockIdx.x * 4;
    const int b   = g0 >> 9;
    const int t0  = g0 & (SS - 1);

    __shared__ float rows2[HH][12];     // [k][x0..x4,pad, r0..r4,pad], 48B stride (16B-aligned)
    __shared__ float part[3][56][32];   // partials from q = 1..3

    // ---- stage rows transposed: thread tid owns k = tid ----
    {
        const int k = tid;
        #pragma unroll
        for (int r = 0; r < 5; r++) {
            int t  = t0 - 1 + r;
            int tc = t < 0 ? 0 : t;
            const size_t gi = (size_t)(b * SS + tc) * HH + k;
            rows2[k][r]     = x[gi];
            rows2[k][6 + r] = ref[gi];
        }
        rows2[k][5]  = 0.f;
        rows2[k][11] = 0.f;
    }
    __syncthreads();

    // ---- accumulators ----
    float A[5][4], C[5][4], P[4][4];
    {
        const float4 ab = (q == 0) ? ((const float4*)b1)[hq]  : make_float4(0.f, 0.f, 0.f, 0.f);
        const float4 pb = (q == 0) ? ((const float4*)bp1)[hq] : make_float4(0.f, 0.f, 0.f, 0.f);
        #pragma unroll
        for (int r = 0; r < 5; r++) {
            A[r][0] = ab.x; A[r][1] = ab.y; A[r][2] = ab.z; A[r][3] = ab.w;
            C[r][0] = 0.f;  C[r][1] = 0.f;  C[r][2] = 0.f;  C[r][3] = 0.f;
        }
        #pragma unroll
        for (int r = 0; r < 4; r++) {
            P[r][0] = pb.x; P[r][1] = pb.y; P[r][2] = pb.z; P[r][3] = pb.w;
        }
    }

    const float4* __restrict__ Wa4 = (const float4*)Wa;   // [k*32 + hq]
    const float4* __restrict__ Wb4 = (const float4*)Wb;
    const float4* __restrict__ Wp4 = (const float4*)Wp1;

    const int kb = q * 32;
    #pragma unroll 2
    for (int kk = 0; kk < 32; kk++) {
        const int k = kb + kk;
        const float4 wa = Wa4[k * 32 + hq];
        const float4 wb = Wb4[k * 32 + hq];
        const float4 wp = Wp4[k * 32 + hq];
        const float4 u0 = *(const float4*)&rows2[k][0];   // x0 x1 x2 x3
        const float4 u1 = *(const float4*)&rows2[k][4];   // x4 pad r0 r1
        const float4 u2 = *(const float4*)&rows2[k][8];   // r2 r3 r4 pad
        const float xv[5]  = {u0.x, u0.y, u0.z, u0.w, u1.x};
        const float rv[5]  = {u1.z, u1.w, u2.x, u2.y, u2.z};
        const float waj[4] = {wa.x, wa.y, wa.z, wa.w};
        const float wbj[4] = {wb.x, wb.y, wb.z, wb.w};
        const float wpj[4] = {wp.x, wp.y, wp.z, wp.w};
        #pragma unroll
        for (int r = 0; r < 5; r++) {
            #pragma unroll
            for (int j = 0; j < 4; j++) {
                A[r][j] = fmaf(xv[r], waj[j], A[r][j]);
                C[r][j] = fmaf(rv[r], wbj[j], C[r][j]);
            }
        }
        #pragma unroll
        for (int r = 0; r < 4; r++) {
            #pragma unroll
            for (int j = 0; j < 4; j++)
                P[r][j] = fmaf(xv[r + 1], wpj[j], P[r][j]);
        }
    }

    // ---- publish partials (q = 1..3) ----
    if (q != 0) {
        #pragma unroll
        for (int r = 0; r < 5; r++) {
            #pragma unroll
            for (int j = 0; j < 4; j++) {
                part[q - 1][r * 4 + j][hq]      = A[r][j];
                part[q - 1][20 + r * 4 + j][hq] = C[r][j];
            }
        }
        #pragma unroll
        for (int r = 0; r < 4; r++) {
            #pragma unroll
            for (int j = 0; j < 4; j++)
                part[q - 1][40 + r * 4 + j][hq] = P[r][j];
        }
    }
    __syncthreads();

    // ---- q == 0: one warp finishes the block ----
    if (q == 0) {
        #pragma unroll
        for (int r = 0; r < 5; r++) {
            #pragma unroll
            for (int j = 0; j < 4; j++) {
                const int d = r * 4 + j;
                A[r][j] += part[0][d][hq]      + part[1][d][hq]      + part[2][d][hq];
                C[r][j] += part[0][20 + d][hq] + part[1][20 + d][hq] + part[2][20 + d][hq];
            }
        }
        #pragma unroll
        for (int r = 0; r < 4; r++) {
            #pragma unroll
            for (int j = 0; j < 4; j++) {
                const int d = 40 + r * 4 + j;
                P[r][j] += part[0][d][hq] + part[1][d][hq] + part[2][d][hq];
                P[r][j]  = fmaxf(P[r][j], 0.f);
            }
        }

        const float4 w2v = ((const float4*)W2)[hq];
        const float  w2a[4] = {w2v.x, w2v.y, w2v.z, w2v.w};
        const float4* wpq = (const float4*)&Wp2[12 * hq];
        const float4 q0v = wpq[0], q1v = wpq[1], q2v = wpq[2];
        const float wq[12] = {q0v.x, q0v.y, q0v.z, q0v.w,
                              q1v.x, q1v.y, q1v.z, q1v.w,
                              q2v.x, q2v.y, q2v.z, q2v.w};
        const float b2s  = b2[0];
        const float bp20 = bp2[0], bp21 = bp2[1], bp22 = bp2[2];

        #pragma unroll
        for (int i = 0; i < 4; i++) {
            const int t = t0 + i;
            float v[6] = {0.f, 0.f, 0.f, 0.f, 0.f, 0.f};
            #pragma unroll
            for (int j = 0; j < 4; j++) {
                v[0] += fmaxf(A[i + 1][j] + C[i + 1][j], 0.f) * w2a[j];  // A[t,t]
                v[1] += fmaxf(A[i][j]     + C[i + 1][j], 0.f) * w2a[j];  // A[t-1,t]
                v[2] += fmaxf(A[i + 1][j] + C[i][j],     0.f) * w2a[j];  // A[t,t-1]
                const float pj = P[i][j];
                v[3] += pj * wq[3 * j + 0];
                v[4] += pj * wq[3 * j + 1];
                v[5] += pj * wq[3 * j + 2];
            }
            #pragma unroll
            for (int j = 0; j < 6; j++) {
                float s = v[j];
                s += __shfl_xor_sync(0xffffffffu, s, 16);
                s += __shfl_xor_sync(0xffffffffu, s, 8);
                s += __shfl_xor_sync(0xffffffffu, s, 4);
                s += __shfl_xor_sync(0xffffffffu, s, 2);
                s += __shfl_xor_sync(0xffffffffu, s, 1);
                v[j] = s;   // all lanes hold the full sum
            }

            // decision, computed redundantly on all 32 lanes
            int   op    = -1;    // -1 => copy x (t == 0)
            float alpha = 0.f;
            const float Ad = 1.0f / (1.0f + expf(-(v[0] + b2s)));
            if (t != 0) {
                const float Ai   = 1.0f / (1.0f + expf(-(v[1] + b2s)));
                const float Adel = 1.0f / (1.0f + expf(-(v[2] + b2s)));
                const float l0 = v[3] + bp20;
                const float l1 = v[4] + bp21;
                const float l2 = v[5] + bp22;
                const float mx  = fmaxf(l0, fmaxf(l1, l2));
                const float lse = mx + logf(expf(l0 - mx) + expf(l1 - mx) + expf(l2 - mx));
                const float m   = Ad   * (l0 - lse);
                const float ins = Ai   * (l1 - lse);
                const float del = Adel * (l2 - lse);
                if (m >= ins && m >= del) op = 0;   // first-max tie-break == jnp.argmax
                else if (ins >= del)      op = 1;
                else                      op = 2;
                alpha = Ad;
            }

            float o[4];
            #pragma unroll
            for (int j = 0; j < 4; j++) {
                const int hcol = 4 * hq + j;
                const float cx = rows2[hcol][i + 1];  // x[t]
                const float cr = rows2[hcol][7 + i];  // ref[t]
                const float px = rows2[hcol][i];      // x[t-1]
                if (op < 0)       o[j] = cx;
                else if (op == 0) o[j] = (1.f - alpha) * cx + alpha * cr;
                else if (op == 1) o[j] = cr;
                else              o[j] = px;
            }
            *(float4*)&out[(size_t)(b * SS + t) * HH + 4 * hq] =
                make_float4(o[0], o[1], o[2], o[3]);
        }
    }
}

extern "C" void kernel_launch(void* const* d_in, const int* in_sizes, int n_in,
                              void* d_out, int out_size) {
    const float* x   = (const float*)d_in[0];
    const float* ref = (const float*)d_in[1];
    const float* Wa  = (const float*)d_in[2];
    const float* Wb  = (const float*)d_in[3];
    const float* b1  = (const float*)d_in[4];
    const float* W2  = (const float*)d_in[5];
    const float* b2  = (const float*)d_in[6];
    const float* Wp1 = (const float*)d_in[7];
    const float* bp1 = (const float*)d_in[8];
    const float* Wp2 = (const float*)d_in[9];
    const float* bp2 = (const float*)d_in[10];

    dim3 grid(BB * SS / 4);   // 512 blocks
    dim3 block(128);          // 32 h-quads x 4 k-quarters
    align_kernel<<<grid, block>>>(x, ref, Wa, Wb, b1, W2, b2,
                                  Wp1, bp1, Wp2, bp2, (float*)d_out);
}